// round 12
// baseline (speedup 1.0000x reference)
#include <cuda_runtime.h>
#include <cuda_fp16.h>
#include <mma.h>
#include <cstdint>

using namespace nvcuda;

// Problem constants
#define CUR    1024
#define FULL   2048
#define BSZ    4
#define DMODEL 1024
#define HN     16
#define HD     64
#define PREV   (FULL - CUR)      // 1024
#define ZB     (BSZ * HN)        // 64 batched heads
#define SCALE  0.125f            // 1/sqrt(64)

// ---------------------------------------------------------------------------
// Scratch
// ---------------------------------------------------------------------------
__device__ __half g_full_h [ (size_t)FULL * BSZ * DMODEL ];
__device__ __half g_in_h   [ (size_t)CUR * BSZ * DMODEL ];
__device__ __half g_pe_h   [ (size_t)FULL * DMODEL ];
__device__ __half g_Wkv_h  [ (size_t)DMODEL * 2 * DMODEL ];
__device__ __half g_Wq_h   [ (size_t)DMODEL * DMODEL ];
__device__ __half g_Wpos_h [ (size_t)DMODEL * DMODEL ];
__device__ __half g_Wproj_h[ (size_t)DMODEL * DMODEL ];

__device__ __half g_kv [ (size_t)FULL * BSZ * 2 * HN * HD ];
__device__ __half g_qu [ (size_t)CUR * BSZ * HN * HD ];
__device__ __half g_qv [ (size_t)CUR * BSZ * HN * HD ];
__device__ __half g_r  [ (size_t)FULL * HN * HD ];
__device__ __half g_ctx[ (size_t)CUR * BSZ * HN * HD ];
__device__ __half g_scores_h[ (size_t)ZB * CUR * FULL ];
__device__ __half g_pos_h   [ (size_t)ZB * CUR * FULL ];
__device__ __half g_probs_h [ (size_t)ZB * CUR * FULL ];
__device__ float  g_beff[ DMODEL ];

#define H(x) __float2half_rn(x)

// cp.async helpers
__device__ __forceinline__ void cp16(void* smem, const void* gmem) {
    uint32_t s = (uint32_t)__cvta_generic_to_shared(smem);
    asm volatile("cp.async.cg.shared.global [%0], [%1], 16;\n" :: "r"(s), "l"(gmem));
}
#define CP_COMMIT asm volatile("cp.async.commit_group;\n" ::: "memory")
#define CP_WAIT1  asm volatile("cp.async.wait_group 1;\n" ::: "memory")
#define CP_WAIT0  asm volatile("cp.async.wait_group 0;\n" ::: "memory")

// ---------------------------------------------------------------------------
// fp32 -> fp16 convert
// ---------------------------------------------------------------------------
__global__ __launch_bounds__(256) void f2h_kernel(
    const float* __restrict__ src, __half* __restrict__ dst, int n4)
{
    int idx = blockIdx.x * 256 + threadIdx.x;
    if (idx < n4) {
        float4 v = reinterpret_cast<const float4*>(src)[idx];
        reinterpret_cast<__half2*>(dst)[idx * 2 + 0] = __floats2half2_rn(v.x, v.y);
        reinterpret_cast<__half2*>(dst)[idx * 2 + 1] = __floats2half2_rn(v.z, v.w);
    }
}

// ---------------------------------------------------------------------------
// FP16 GEMM, KC=64, cp.async double-buffered: C = A @ B
// 128x128 tile, 8 warps each 64x32. Dynamic smem (~80 KB).
// ---------------------------------------------------------------------------
#define GEMM_SMEM_BYTES (2 * (128 * 72 + 64 * 136) * 2 + 8 * 256 * 4)

template<bool OUT_HALF>
__global__ __launch_bounds__(256) void gemm_hh(
    const __half* __restrict__ A, const __half* __restrict__ B,
    void* __restrict__ Cv, int M, int N, int K)
{
    extern __shared__ __half dyn_h[];
    __half* sA = dyn_h;                               // [2][128*72]
    __half* sB = dyn_h + 2 * 128 * 72;                // [2][64*136]
    float*  stg = reinterpret_cast<float*>(dyn_h + 2 * 128 * 72 + 2 * 64 * 136); // [8][256]

    int tid = threadIdx.x, warp = tid >> 5, lid = tid & 31;
    int wm = warp >> 2, wn = warp & 3;
    int m0 = blockIdx.y * 128, n0 = blockIdx.x * 128;

    wmma::fragment<wmma::accumulator, 16, 16, 16, float> acc[4][2];
#pragma unroll
    for (int i = 0; i < 4; i++)
#pragma unroll
        for (int j = 0; j < 2; j++) wmma::fill_fragment(acc[i][j], 0.f);

    int am = tid >> 1,  ak = (tid & 1) * 32;   // A: 128 rows x 64 k, 32 h/thread
    int bk = tid >> 2,  bn = (tid & 3) * 32;   // B: 64 k x 128 n, 32 h/thread
    const __half* Abase = A + (size_t)(m0 + am) * K + ak;
    const __half* Bbase = B + (size_t)bk * N + n0 + bn;

    int KT = K >> 6;   // chunks of 64
    {
        __half* da = sA + am * 72 + ak;
        __half* db = sB + bk * 136 + bn;
#pragma unroll
        for (int s = 0; s < 4; s++) cp16(da + 8 * s, Abase + 8 * s);
#pragma unroll
        for (int s = 0; s < 4; s++) cp16(db + 8 * s, Bbase + 8 * s);
        CP_COMMIT;
    }

    for (int kt = 0; kt < KT; kt++) {
        if (kt + 1 < KT) {
            int buf = (kt + 1) & 1, k0 = (kt + 1) << 6;
            const __half* ap = Abase + k0;
            const __half* bp = Bbase + (size_t)k0 * N;
            __half* da = sA + buf * (128 * 72) + am * 72 + ak;
            __half* db = sB + buf * (64 * 136) + bk * 136 + bn;
#pragma unroll
            for (int s = 0; s < 4; s++) cp16(da + 8 * s, ap + 8 * s);
#pragma unroll
            for (int s = 0; s < 4; s++) cp16(db + 8 * s, bp + 8 * s);
            CP_COMMIT;
            CP_WAIT1;
        } else {
            CP_WAIT0;
        }
        __syncthreads();
        const __half* cA = sA + (kt & 1) * (128 * 72);
        const __half* cB = sB + (kt & 1) * (64 * 136);
#pragma unroll
        for (int kk = 0; kk < 4; kk++) {
            wmma::fragment<wmma::matrix_a, 16, 16, 16, __half, wmma::row_major> af[4];
            wmma::fragment<wmma::matrix_b, 16, 16, 16, __half, wmma::row_major> bf[2];
#pragma unroll
            for (int i = 0; i < 4; i++)
                wmma::load_matrix_sync(af[i], &cA[(wm * 64 + i * 16) * 72 + kk * 16], 72);
#pragma unroll
            for (int j = 0; j < 2; j++)
                wmma::load_matrix_sync(bf[j], &cB[(kk * 16) * 136 + wn * 32 + j * 16], 136);
#pragma unroll
            for (int i = 0; i < 4; i++)
#pragma unroll
                for (int j = 0; j < 2; j++)
                    wmma::mma_sync(acc[i][j], af[i], bf[j], acc[i][j]);
        }
        __syncthreads();
    }

    if (OUT_HALF) {
        __half* C = reinterpret_cast<__half*>(Cv);
        float* w = stg + warp * 256;
        int rr = lid >> 1, cc = (lid & 1) * 8;
#pragma unroll
        for (int i = 0; i < 4; i++)
#pragma unroll
            for (int j = 0; j < 2; j++) {
                wmma::store_matrix_sync(w, acc[i][j], 16, wmma::mem_row_major);
                __syncwarp();
                const float* src = w + rr * 16 + cc;
                __half* dst = C + (size_t)(m0 + wm * 64 + i * 16 + rr) * N
                                + n0 + wn * 32 + j * 16 + cc;
#pragma unroll
                for (int t = 0; t < 8; t += 2)
                    *reinterpret_cast<__half2*>(dst + t) = __floats2half2_rn(src[t], src[t + 1]);
                __syncwarp();
            }
    } else {
        float* C = reinterpret_cast<float*>(Cv);
#pragma unroll
        for (int i = 0; i < 4; i++)
#pragma unroll
            for (int j = 0; j < 2; j++)
                wmma::store_matrix_sync(
                    C + (size_t)(m0 + wm * 64 + i * 16) * N + n0 + wn * 32 + j * 16,
                    acc[i][j], N, wmma::mem_row_major);
    }
}

// ---------------------------------------------------------------------------
// q-projection GEMM with fused qu/qv epilogue:
//   qu = A@B + (b_q + u)[n], qv = A@B + (b_q + v)[n], fp16 outputs. N = K = 1024.
// ---------------------------------------------------------------------------
__global__ __launch_bounds__(256) void gemm_quv(
    const __half* __restrict__ A, const __half* __restrict__ B,
    const float* __restrict__ b_q, const float* __restrict__ u,
    const float* __restrict__ v,
    __half* __restrict__ qu, __half* __restrict__ qv)
{
    const int N = DMODEL, K = DMODEL;
    extern __shared__ __half dyn_h[];
    __half* sA = dyn_h;
    __half* sB = dyn_h + 2 * 128 * 72;
    float*  stg = reinterpret_cast<float*>(dyn_h + 2 * 128 * 72 + 2 * 64 * 136);

    int tid = threadIdx.x, warp = tid >> 5, lid = tid & 31;
    int wm = warp >> 2, wn = warp & 3;
    int m0 = blockIdx.y * 128, n0 = blockIdx.x * 128;

    wmma::fragment<wmma::accumulator, 16, 16, 16, float> acc[4][2];
#pragma unroll
    for (int i = 0; i < 4; i++)
#pragma unroll
        for (int j = 0; j < 2; j++) wmma::fill_fragment(acc[i][j], 0.f);

    int am = tid >> 1,  ak = (tid & 1) * 32;
    int bk = tid >> 2,  bn = (tid & 3) * 32;
    const __half* Abase = A + (size_t)(m0 + am) * K + ak;
    const __half* Bbase = B + (size_t)bk * N + n0 + bn;

    int KT = K >> 6;
    {
        __half* da = sA + am * 72 + ak;
        __half* db = sB + bk * 136 + bn;
#pragma unroll
        for (int s = 0; s < 4; s++) cp16(da + 8 * s, Abase + 8 * s);
#pragma unroll
        for (int s = 0; s < 4; s++) cp16(db + 8 * s, Bbase + 8 * s);
        CP_COMMIT;
    }

    for (int kt = 0; kt < KT; kt++) {
        if (kt + 1 < KT) {
            int buf = (kt + 1) & 1, k0 = (kt + 1) << 6;
            const __half* ap = Abase + k0;
            const __half* bp = Bbase + (size_t)k0 * N;
            __half* da = sA + buf * (128 * 72) + am * 72 + ak;
            __half* db = sB + buf * (64 * 136) + bk * 136 + bn;
#pragma unroll
            for (int s = 0; s < 4; s++) cp16(da + 8 * s, ap + 8 * s);
#pragma unroll
            for (int s = 0; s < 4; s++) cp16(db + 8 * s, bp + 8 * s);
            CP_COMMIT;
            CP_WAIT1;
        } else {
            CP_WAIT0;
        }
        __syncthreads();
        const __half* cA = sA + (kt & 1) * (128 * 72);
        const __half* cB = sB + (kt & 1) * (64 * 136);
#pragma unroll
        for (int kk = 0; kk < 4; kk++) {
            wmma::fragment<wmma::matrix_a, 16, 16, 16, __half, wmma::row_major> af[4];
            wmma::fragment<wmma::matrix_b, 16, 16, 16, __half, wmma::row_major> bf[2];
#pragma unroll
            for (int i = 0; i < 4; i++)
                wmma::load_matrix_sync(af[i], &cA[(wm * 64 + i * 16) * 72 + kk * 16], 72);
#pragma unroll
            for (int j = 0; j < 2; j++)
                wmma::load_matrix_sync(bf[j], &cB[(kk * 16) * 136 + wn * 32 + j * 16], 136);
#pragma unroll
            for (int i = 0; i < 4; i++)
#pragma unroll
                for (int j = 0; j < 2; j++)
                    wmma::mma_sync(acc[i][j], af[i], bf[j], acc[i][j]);
        }
        __syncthreads();
    }

    float* w = stg + warp * 256;
    int rr = lid >> 1, cc = (lid & 1) * 8;
#pragma unroll
    for (int i = 0; i < 4; i++)
#pragma unroll
        for (int j = 0; j < 2; j++) {
            wmma::store_matrix_sync(w, acc[i][j], 16, wmma::mem_row_major);
            __syncwarp();
            const float* src = w + rr * 16 + cc;
            size_t row = (size_t)(m0 + wm * 64 + i * 16 + rr) * N;
            int n = n0 + wn * 32 + j * 16 + cc;
#pragma unroll
            for (int t = 0; t < 8; t += 2) {
                float a0 = src[t]     + b_q[n + t];
                float a1 = src[t + 1] + b_q[n + t + 1];
                *reinterpret_cast<__half2*>(qu + row + n + t) =
                    __floats2half2_rn(a0 + u[n + t], a1 + u[n + t + 1]);
                *reinterpret_cast<__half2*>(qv + row + n + t) =
                    __floats2half2_rn(a0 + v[n + t], a1 + v[n + t + 1]);
            }
            __syncwarp();
        }
}

// ---------------------------------------------------------------------------
__global__ __launch_bounds__(256) void beff_kernel(
    const float* __restrict__ b_kv, const float* __restrict__ W_proj,
    const float* __restrict__ b_proj, float* __restrict__ beff)
{
    int n = blockIdx.x * 256 + threadIdx.x;
    float acc = b_proj[n];
    for (int m = 0; m < DMODEL; m++)
        acc += b_kv[DMODEL + m] * W_proj[(size_t)m * DMODEL + n];
    beff[n] = acc;
}

__global__ __launch_bounds__(256) void bias_add_kernel(
    float* __restrict__ out, const float* __restrict__ beff)
{
    int idx = blockIdx.x * 256 + threadIdx.x;
    int n4 = idx & 255;
    float4 o = reinterpret_cast<float4*>(out)[idx];
    float4 b = reinterpret_cast<const float4*>(beff)[n4];
    o.x += b.x; o.y += b.y; o.z += b.z; o.w += b.w;
    reinterpret_cast<float4*>(out)[idx] = o;
}

// ---------------------------------------------------------------------------
// Score GEMM (fp16 in/out), single-shot K=64.  (unchanged R11)
// ---------------------------------------------------------------------------
#define SCORE_SMEM_BYTES (128 * 132 * 4)
__global__ __launch_bounds__(256) void score_h(
    const __half* __restrict__ QU, const __half* __restrict__ SRC,
    __half* __restrict__ OUT, int isPos)
{
    int i0 = blockIdx.y * 128, j0 = blockIdx.x * 128;
    if (!isPos && j0 >= i0 + 1152) return;
    if (isPos && (i0 + j0 + 254) < 1023) return;
    int z = blockIdx.z;
    int b = z >> 4, h = z & 15;
    const __half* A0 = QU + b * DMODEL + h * HD;
    const __half* B0 = isPos ? (SRC + h * HD) : (SRC + b * 2048 + h * HD);
    size_t ldB = isPos ? (size_t)(HN * HD) : (size_t)(BSZ * 2 * HN * HD);

    extern __shared__ char dynsm[];
    __half* sA = reinterpret_cast<__half*>(dynsm);           // 128 x 72
    __half* sB = sA + 128 * 72;
    float*  stage = reinterpret_cast<float*>(dynsm);

    int tid = threadIdx.x, warp = tid >> 5;
    int wm = warp >> 2, wn = warp & 3;

    wmma::fragment<wmma::accumulator, 16, 16, 16, float> acc[4][2];
#pragma unroll
    for (int i = 0; i < 4; i++)
#pragma unroll
        for (int j = 0; j < 2; j++) wmma::fill_fragment(acc[i][j], 0.f);

    int rm = tid >> 1, rk = (tid & 1) * 32;
    {
        const __half* ap = A0 + (size_t)(i0 + rm) * (BSZ * DMODEL) + rk;
        __half* sa = sA + rm * 72 + rk;
#pragma unroll
        for (int s = 0; s < 4; s++)
            *reinterpret_cast<uint4*>(sa + 8 * s) = *reinterpret_cast<const uint4*>(ap + 8 * s);
        const __half* bp = B0 + (size_t)(j0 + rm) * ldB + rk;
        __half* sb = sB + rm * 72 + rk;
#pragma unroll
        for (int s = 0; s < 4; s++)
            *reinterpret_cast<uint4*>(sb + 8 * s) = *reinterpret_cast<const uint4*>(bp + 8 * s);
    }
    __syncthreads();
#pragma unroll
    for (int kk = 0; kk < 4; kk++) {
        wmma::fragment<wmma::matrix_a, 16, 16, 16, __half, wmma::row_major> af[4];
        wmma::fragment<wmma::matrix_b, 16, 16, 16, __half, wmma::col_major> bf[2];
#pragma unroll
        for (int i = 0; i < 4; i++)
            wmma::load_matrix_sync(af[i], &sA[(wm * 64 + i * 16) * 72 + kk * 16], 72);
#pragma unroll
        for (int j = 0; j < 2; j++)
            wmma::load_matrix_sync(bf[j], &sB[(wn * 32 + j * 16) * 72 + kk * 16], 72);
#pragma unroll
        for (int i = 0; i < 4; i++)
#pragma unroll
            for (int j = 0; j < 2; j++)
                wmma::mma_sync(acc[i][j], af[i], bf[j], acc[i][j]);
    }
    __syncthreads();

#pragma unroll
    for (int i = 0; i < 4; i++)
#pragma unroll
        for (int j = 0; j < 2; j++)
            wmma::store_matrix_sync(&stage[(wm * 64 + i * 16) * 132 + wn * 32 + j * 16],
                                    acc[i][j], 132, wmma::mem_row_major);
    __syncthreads();

    __half* C0 = OUT + (size_t)z * CUR * FULL;
    int row = tid >> 1, cb = (tid & 1) * 64;
    __half* dst = C0 + (size_t)(i0 + row) * FULL + j0 + cb;
    const float* src = stage + row * 132 + cb;
#pragma unroll
    for (int t = 0; t < 64; t += 2)
        *reinterpret_cast<__half2*>(dst + t) = __floats2half2_rn(src[t], src[t + 1]);
}

// ---------------------------------------------------------------------------
// Fused rel_shift gather + mask + softmax; writes only columns the ctx GEMM
// reads: [0, (i & ~127) + 1152).
// ---------------------------------------------------------------------------
__global__ __launch_bounds__(256) void softmax_kernel(
    const __half* __restrict__ cont, const __half* __restrict__ pos,
    __half* __restrict__ out)
{
    int i = blockIdx.x;
    int z = blockIdx.y;
    int tid = threadIdx.x;
    size_t rowOff = ((size_t)z * CUR + i) * FULL;
    const __half* c = cont + rowOff;
    const __half* p = pos + rowOff;
    int jmax  = i + PREV;
    int shift = CUR - 1 - i;
    int WR = (i & ~127) + 1152;  if (WR > FULL) WR = FULL;

    float vals[8];
    float mx = -1e30f;
#pragma unroll
    for (int it = 0; it < 8; it++) {
        int j = tid + it * 256;
        float s = -1e30f;
        if (j <= jmax)
            s = (__half2float(c[j]) + __half2float(p[j + shift])) * SCALE;
        vals[it] = s;
        mx = fmaxf(mx, s);
    }
    __shared__ float redm[8];
    __shared__ float reds[8];
#pragma unroll
    for (int o = 16; o; o >>= 1) mx = fmaxf(mx, __shfl_xor_sync(0xffffffffu, mx, o));
    if ((tid & 31) == 0) redm[tid >> 5] = mx;
    __syncthreads();
    mx = redm[0];
#pragma unroll
    for (int w = 1; w < 8; w++) mx = fmaxf(mx, redm[w]);

    float sum = 0.f;
#pragma unroll
    for (int it = 0; it < 8; it++) {
        float e = __expf(vals[it] - mx);
        vals[it] = e;
        sum += e;
    }
#pragma unroll
    for (int o = 16; o; o >>= 1) sum += __shfl_xor_sync(0xffffffffu, sum, o);
    if ((tid & 31) == 0) reds[tid >> 5] = sum;
    __syncthreads();
    sum = 0.f;
#pragma unroll
    for (int w = 0; w < 8; w++) sum += reds[w];
    float inv = 1.f / sum;

    __half* o = out + rowOff;
#pragma unroll
    for (int it = 0; it < 8; it++) {
        int j = tid + it * 256;
        if (j < WR)
            o[j] = (j <= jmax) ? H(vals[it] * inv) : __half(0.f);
    }
}

// ---------------------------------------------------------------------------
// Context GEMM fp16, cp.async double-buffered. K truncated at i0+1152. (R11)
// ---------------------------------------------------------------------------
__global__ __launch_bounds__(256) void ctx_h(
    const __half* __restrict__ probs, const __half* __restrict__ kv,
    __half* __restrict__ ctx)
{
    int z = blockIdx.y;
    int b = z >> 4, h = z & 15;
    int i0 = blockIdx.x * 128;
    const __half* A0 = probs + (size_t)z * CUR * FULL;
    const __half* B0 = kv + (size_t)b * 2048 + DMODEL + h * HD;

    __shared__ __half sA[2][128 * 40];
    __shared__ __half sB[2][32 * 72];
    __shared__ float  stg[8][256];
    int tid = threadIdx.x, warp = tid >> 5, lid = tid & 31;
    int wm = warp >> 1, wn = warp & 1;

    wmma::fragment<wmma::accumulator, 16, 16, 16, float> acc[2][2];
#pragma unroll
    for (int i = 0; i < 2; i++)
#pragma unroll
        for (int j = 0; j < 2; j++) wmma::fill_fragment(acc[i][j], 0.f);

    int am = tid >> 1, aj = (tid & 1) * 16;
    int bj = tid >> 3, bd = (tid & 7) * 8;
    const __half* Abase = A0 + (size_t)(i0 + am) * FULL + aj;
    const __half* Bbase = B0 + (size_t)bj * (BSZ * 2 * HN * HD) + bd;
    const size_t bstr = (size_t)(BSZ * 2 * HN * HD);

    int kmax = i0 + 1152;  if (kmax > FULL) kmax = FULL;
    int KT = kmax >> 5;

    cp16(&sA[0][am * 40 + aj],     Abase);
    cp16(&sA[0][am * 40 + aj + 8], Abase + 8);
    cp16(&sB[0][bj * 72 + bd],     Bbase);
    CP_COMMIT;

    for (int kt = 0; kt < KT; kt++) {
        if (kt + 1 < KT) {
            int buf = (kt + 1) & 1, k0 = (kt + 1) << 5;
            const __half* ap = Abase + k0;
            const __half* bp = Bbase + (size_t)k0 * bstr;
            cp16(&sA[buf][am * 40 + aj],     ap);
            cp16(&sA[buf][am * 40 + aj + 8], ap + 8);
            cp16(&sB[buf][bj * 72 + bd],     bp);
            CP_COMMIT;
            CP_WAIT1;
        } else {
            CP_WAIT0;
        }
        __syncthreads();
        int cb = kt & 1;
#pragma unroll
        for (int kk = 0; kk < 2; kk++) {
            wmma::fragment<wmma::matrix_a, 16, 16, 16, __half, wmma::row_major> af[2];
            wmma::fragment<wmma::matrix_b, 16, 16, 16, __half, wmma::row_major> bf[2];
#pragma unroll
            for (int i = 0; i < 2; i++)
                wmma::load_matrix_sync(af[i], &sA[cb][(wm * 32 + i * 16) * 40 + kk * 16], 40);
#pragma unroll
            for (int j = 0; j < 2; j++)
                wmma::load_matrix_sync(bf[j], &sB[cb][(kk * 16) * 72 + wn * 32 + j * 16], 72);
#pragma unroll
            for (int i = 0; i < 2; i++)
#pragma unroll
                for (int j = 0; j < 2; j++)
                    wmma::mma_sync(acc[i][j], af[i], bf[j], acc[i][j]);
        }
        __syncthreads();
    }
    int rr = lid >> 1, cc = (lid & 1) * 8;
#pragma unroll
    for (int i = 0; i < 2; i++)
#pragma unroll
        for (int j = 0; j < 2; j++) {
            wmma::store_matrix_sync(&stg[warp][0], acc[i][j], 16, wmma::mem_row_major);
            __syncwarp();
            const float* src = &stg[warp][rr * 16 + cc];
            __half* dst = ctx + (size_t)((i0 + wm * 32 + i * 16 + rr) * BSZ + b) * DMODEL
                              + h * HD + wn * 32 + j * 16 + cc;
#pragma unroll
            for (int t = 0; t < 8; t += 2)
                *reinterpret_cast<__half2*>(dst + t) = __floats2half2_rn(src[t], src[t + 1]);
            __syncwarp();
        }
}

// ---------------------------------------------------------------------------
// Launch
// ---------------------------------------------------------------------------
extern "C" void kernel_launch(void* const* d_in, const int* in_sizes, int n_in,
                              void* d_out, int out_size)
{
    const float* inputs  = (const float*)d_in[0];
    const float* pos_emb = (const float*)d_in[1];
    const float* full_in = (const float*)d_in[2];
    const float* u       = (const float*)d_in[3];
    const float* v       = (const float*)d_in[4];
    const float* W_kv    = (const float*)d_in[6];
    const float* b_kv    = (const float*)d_in[7];
    const float* W_q     = (const float*)d_in[8];
    const float* b_q     = (const float*)d_in[9];
    const float* W_pos   = (const float*)d_in[10];
    const float* W_proj  = (const float*)d_in[12];
    const float* b_proj  = (const float*)d_in[13];
    float* out = (float*)d_out;

    float *beff;
    __half *fullh, *inh, *peh, *Wkvh, *Wqh, *Wposh, *Wprojh;
    __half *kv, *qu, *qv, *r, *ctx, *scores, *pos, *probs;
    cudaGetSymbolAddress((void**)&fullh,  g_full_h);
    cudaGetSymbolAddress((void**)&inh,    g_in_h);
    cudaGetSymbolAddress((void**)&peh,    g_pe_h);
    cudaGetSymbolAddress((void**)&Wkvh,   g_Wkv_h);
    cudaGetSymbolAddress((void**)&Wqh,    g_Wq_h);
    cudaGetSymbolAddress((void**)&Wposh,  g_Wpos_h);
    cudaGetSymbolAddress((void**)&Wprojh, g_Wproj_h);
    cudaGetSymbolAddress((void**)&kv,     g_kv);
    cudaGetSymbolAddress((void**)&qu,     g_qu);
    cudaGetSymbolAddress((void**)&qv,     g_qv);
    cudaGetSymbolAddress((void**)&r,      g_r);
    cudaGetSymbolAddress((void**)&ctx,    g_ctx);
    cudaGetSymbolAddress((void**)&scores, g_scores_h);
    cudaGetSymbolAddress((void**)&pos,    g_pos_h);
    cudaGetSymbolAddress((void**)&probs,  g_probs_h);
    cudaGetSymbolAddress((void**)&beff,   g_beff);

    static int attr_set = 0;
    if (!attr_set) {
        cudaFuncSetAttribute(score_h, cudaFuncAttributeMaxDynamicSharedMemorySize,
                             SCORE_SMEM_BYTES);
        cudaFuncSetAttribute(gemm_hh<true>, cudaFuncAttributeMaxDynamicSharedMemorySize,
                             GEMM_SMEM_BYTES);
        cudaFuncSetAttribute(gemm_hh<false>, cudaFuncAttributeMaxDynamicSharedMemorySize,
                             GEMM_SMEM_BYTES);
        cudaFuncSetAttribute(gemm_quv, cudaFuncAttributeMaxDynamicSharedMemorySize,
                             GEMM_SMEM_BYTES);
        attr_set = 1;
    }

    // fp32 -> fp16 converts
    f2h_kernel<<<(8192 * 1024 / 4) / 256, 256>>>(full_in, fullh, 8192 * 1024 / 4);
    f2h_kernel<<<(4096 * 1024 / 4) / 256, 256>>>(inputs, inh, 4096 * 1024 / 4);
    f2h_kernel<<<(2048 * 1024 / 4) / 256, 256>>>(pos_emb, peh, 2048 * 1024 / 4);
    f2h_kernel<<<(1024 * 2048 / 4) / 256, 256>>>(W_kv, Wkvh, 1024 * 2048 / 4);
    f2h_kernel<<<(1024 * 1024 / 4) / 256, 256>>>(W_q, Wqh, 1024 * 1024 / 4);
    f2h_kernel<<<(1024 * 1024 / 4) / 256, 256>>>(W_pos, Wposh, 1024 * 1024 / 4);
    f2h_kernel<<<(1024 * 1024 / 4) / 256, 256>>>(W_proj, Wprojh, 1024 * 1024 / 4);

    // Projections
    gemm_hh<true ><<<dim3(2048 / 128, 8192 / 128), 256, GEMM_SMEM_BYTES>>>(fullh, Wkvh, kv, 8192, 2048, 1024);
    gemm_quv<<<dim3(1024 / 128, 4096 / 128), 256, GEMM_SMEM_BYTES>>>(inh, Wqh, b_q, u, v, qu, qv);
    gemm_hh<true ><<<dim3(1024 / 128, 2048 / 128), 256, GEMM_SMEM_BYTES>>>(peh, Wposh, r, 2048, 1024, 1024);

    beff_kernel<<<DMODEL / 256, 256>>>(b_kv, W_proj, b_proj, beff);

    // Scores (fp16 in/out)
    score_h<<<dim3(FULL / 128, CUR / 128, ZB), 256, SCORE_SMEM_BYTES>>>(qu, kv, scores, 0);
    score_h<<<dim3(FULL / 128, CUR / 128, ZB), 256, SCORE_SMEM_BYTES>>>(qv, r, pos, 1);

    // shift + mask + softmax -> fp16 probs
    softmax_kernel<<<dim3(CUR, ZB), 256>>>(scores, pos, probs);

    // ctx = probs @ val
    ctx_h<<<dim3(CUR / 128, ZB), 256>>>(probs, kv, ctx);

    // out = ctx @ W_proj + b_eff
    gemm_hh<false><<<dim3(1024 / 128, 4096 / 128), 256, GEMM_SMEM_BYTES>>>(ctx, Wprojh, out, 4096, 1024, 1024);
    bias_add_kernel<<<4096, 256>>>(out, beff);

    (void)in_sizes; (void)n_in; (void)out_size;
}